// round 1
// baseline (speedup 1.0000x reference)
#include <cuda_runtime.h>

#define EPSBN 1e-5f
#define HH 300
#define WW 300
#define BB 4
#define C1 256
#define HC 64
#define TILE 16
#define CBLK 8
#define NTILE 19   // ceil(300/16)

// Intermediate "shared trunk" activation: [B, HC, H, W] = 92.16 MB
__device__ float g_trunk[(size_t)BB * HC * HH * WW];

// ---------------------------------------------------------------------------
// Kernel 1: conv3x3 (C1=256 -> HC=64) + BN + ReLU  -> g_trunk
// Block = 256 threads = 16x16 output tile, all 64 output channels per thread.
// ---------------------------------------------------------------------------
__global__ __launch_bounds__(256) void conv1_kernel(
    const float* __restrict__ bev, const float* __restrict__ wgt,
    const float* __restrict__ gg, const float* __restrict__ bb,
    const float* __restrict__ mm, const float* __restrict__ vv)
{
    __shared__ float s_in[CBLK][18 * 19];
    __shared__ float s_w[CBLK][9 * 68];
    __shared__ float s_scale[HC], s_shift[HC];

    const int tid = threadIdx.x;
    const int tx = tid & 15, ty = tid >> 4;
    const int bx = blockIdx.x * TILE, by = blockIdx.y * TILE;
    const int b = blockIdx.z;

    if (tid < HC) {
        float sc = gg[tid] * rsqrtf(vv[tid] + EPSBN);
        s_scale[tid] = sc;
        s_shift[tid] = bb[tid] - mm[tid] * sc;
    }

    float acc[HC];
#pragma unroll
    for (int i = 0; i < HC; i++) acc[i] = 0.f;

    const float* inb = bev + (size_t)b * C1 * HH * WW;

    for (int cc = 0; cc < C1; cc += CBLK) {
        __syncthreads();
        // stage input halo tile for CBLK channels
        for (int i = tid; i < CBLK * 18 * 18; i += 256) {
            int c = i / 324;
            int rem = i % 324;
            int r = rem / 18;
            int col = rem % 18;
            int gy = by - 1 + r, gx = bx - 1 + col;
            float val = 0.f;
            if ((unsigned)gy < HH && (unsigned)gx < WW)
                val = inb[(size_t)(cc + c) * HH * WW + gy * WW + gx];
            s_in[c][r * 19 + col] = val;
        }
        // stage weights: dest s_w[c][k*68 + oc], src wgt[oc*C1*9 + (cc+c)*9 + k]
        for (int i = tid; i < CBLK * 9 * HC; i += 256) {
            int c = i / (9 * HC);
            int j = i % (9 * HC);
            int oc = j / 9, k = j % 9;
            s_w[c][k * 68 + oc] = wgt[(size_t)oc * (C1 * 9) + (cc + c) * 9 + k];
        }
        __syncthreads();

#pragma unroll 1
        for (int c = 0; c < CBLK; c++) {
            float p[9];
#pragma unroll
            for (int dy = 0; dy < 3; dy++)
#pragma unroll
                for (int dx = 0; dx < 3; dx++)
                    p[dy * 3 + dx] = s_in[c][(ty + dy) * 19 + tx + dx];
#pragma unroll
            for (int k = 0; k < 9; k++) {
#pragma unroll
                for (int o4 = 0; o4 < 16; o4++) {
                    float4 w4 = *(const float4*)&s_w[c][k * 68 + o4 * 4];
                    acc[o4 * 4 + 0] += p[k] * w4.x;
                    acc[o4 * 4 + 1] += p[k] * w4.y;
                    acc[o4 * 4 + 2] += p[k] * w4.z;
                    acc[o4 * 4 + 3] += p[k] * w4.w;
                }
            }
        }
    }

    const int gy = by + ty, gx = bx + tx;
    if (gy < HH && gx < WW) {
        float* outb = g_trunk + (size_t)b * HC * HH * WW + gy * WW + gx;
#pragma unroll
        for (int oc = 0; oc < HC; oc++) {
            float r = fmaxf(acc[oc] * s_scale[oc] + s_shift[oc], 0.f);
            outb[(size_t)oc * HH * WW] = r;
        }
    }
}

// ---------------------------------------------------------------------------
// Head kernel: conv3x3 (HC->HC) + BN + ReLU + conv1x1 (HC->NOUT) + bias
// ---------------------------------------------------------------------------
template <int NOUT>
__global__ __launch_bounds__(256) void head_kernel(
    const float* __restrict__ w1,
    const float* __restrict__ gg, const float* __restrict__ bb,
    const float* __restrict__ mm, const float* __restrict__ vv,
    const float* __restrict__ w2, const float* __restrict__ b2,
    float* __restrict__ out)
{
    __shared__ float s_in[CBLK][18 * 19];
    __shared__ float s_w[CBLK][9 * 68];
    __shared__ float s_scale[HC], s_shift[HC];
    __shared__ float s_w2[NOUT * HC];
    __shared__ float s_b2[NOUT];

    const int tid = threadIdx.x;
    const int tx = tid & 15, ty = tid >> 4;
    const int bx = blockIdx.x * TILE, by = blockIdx.y * TILE;
    const int b = blockIdx.z;

    if (tid < HC) {
        float sc = gg[tid] * rsqrtf(vv[tid] + EPSBN);
        s_scale[tid] = sc;
        s_shift[tid] = bb[tid] - mm[tid] * sc;
    }
    for (int i = tid; i < NOUT * HC; i += 256) s_w2[i] = w2[i];
    if (tid < NOUT) s_b2[tid] = b2[tid];

    float acc[HC];
#pragma unroll
    for (int i = 0; i < HC; i++) acc[i] = 0.f;

    const float* inb = g_trunk + (size_t)b * HC * HH * WW;

    for (int cc = 0; cc < HC; cc += CBLK) {
        __syncthreads();
        for (int i = tid; i < CBLK * 18 * 18; i += 256) {
            int c = i / 324;
            int rem = i % 324;
            int r = rem / 18;
            int col = rem % 18;
            int gy = by - 1 + r, gx = bx - 1 + col;
            float val = 0.f;
            if ((unsigned)gy < HH && (unsigned)gx < WW)
                val = inb[(size_t)(cc + c) * HH * WW + gy * WW + gx];
            s_in[c][r * 19 + col] = val;
        }
        for (int i = tid; i < CBLK * 9 * HC; i += 256) {
            int c = i / (9 * HC);
            int j = i % (9 * HC);
            int oc = j / 9, k = j % 9;
            s_w[c][k * 68 + oc] = w1[(size_t)oc * (HC * 9) + (cc + c) * 9 + k];
        }
        __syncthreads();

#pragma unroll 1
        for (int c = 0; c < CBLK; c++) {
            float p[9];
#pragma unroll
            for (int dy = 0; dy < 3; dy++)
#pragma unroll
                for (int dx = 0; dx < 3; dx++)
                    p[dy * 3 + dx] = s_in[c][(ty + dy) * 19 + tx + dx];
#pragma unroll
            for (int k = 0; k < 9; k++) {
#pragma unroll
                for (int o4 = 0; o4 < 16; o4++) {
                    float4 w4 = *(const float4*)&s_w[c][k * 68 + o4 * 4];
                    acc[o4 * 4 + 0] += p[k] * w4.x;
                    acc[o4 * 4 + 1] += p[k] * w4.y;
                    acc[o4 * 4 + 2] += p[k] * w4.z;
                    acc[o4 * 4 + 3] += p[k] * w4.w;
                }
            }
        }
    }

    // BN + ReLU on mid activations (in place)
#pragma unroll
    for (int oc = 0; oc < HC; oc++)
        acc[oc] = fmaxf(acc[oc] * s_scale[oc] + s_shift[oc], 0.f);

    const int gy = by + ty, gx = bx + tx;
    const bool ok = (gy < HH) && (gx < WW);

    // 1x1 conv + bias
#pragma unroll
    for (int c = 0; c < NOUT; c++) {
        float s = s_b2[c];
#pragma unroll
        for (int o4 = 0; o4 < 16; o4++) {
            float4 w4 = *(const float4*)&s_w2[c * HC + o4 * 4];
            s += acc[o4 * 4 + 0] * w4.x + acc[o4 * 4 + 1] * w4.y +
                 acc[o4 * 4 + 2] * w4.z + acc[o4 * 4 + 3] * w4.w;
        }
        if (ok)
            out[((size_t)(b * NOUT + c) * HH + gy) * WW + gx] = s;
    }
}

// ---------------------------------------------------------------------------
extern "C" void kernel_launch(void* const* d_in, const int* in_sizes, int n_in,
                              void* d_out, int out_size)
{
    const float* bev     = (const float*)d_in[0];
    const float* w_sh    = (const float*)d_in[1];
    const float* g_sh    = (const float*)d_in[2];
    const float* b_sh    = (const float*)d_in[3];
    const float* m_sh    = (const float*)d_in[4];
    const float* v_sh    = (const float*)d_in[5];
    const float* w_hm1   = (const float*)d_in[6];
    const float* g_hm1   = (const float*)d_in[7];
    const float* b_hm1   = (const float*)d_in[8];
    const float* m_hm1   = (const float*)d_in[9];
    const float* v_hm1   = (const float*)d_in[10];
    const float* w_hm2   = (const float*)d_in[11];
    const float* b_hm2   = (const float*)d_in[12];
    const float* w_reg1  = (const float*)d_in[13];
    const float* g_reg1  = (const float*)d_in[14];
    const float* b_reg1  = (const float*)d_in[15];
    const float* m_reg1  = (const float*)d_in[16];
    const float* v_reg1  = (const float*)d_in[17];
    const float* w_reg2  = (const float*)d_in[18];
    const float* b_reg2  = (const float*)d_in[19];

    float* out = (float*)d_out;
    float* heatmap = out;                                   // [4,3,300,300]
    float* box_reg = out + (size_t)BB * 3 * HH * WW;        // [4,8,300,300]

    dim3 grid(NTILE, NTILE, BB);
    conv1_kernel<<<grid, 256>>>(bev, w_sh, g_sh, b_sh, m_sh, v_sh);
    head_kernel<3><<<grid, 256>>>(w_hm1, g_hm1, b_hm1, m_hm1, v_hm1,
                                  w_hm2, b_hm2, heatmap);
    head_kernel<8><<<grid, 256>>>(w_reg1, g_reg1, b_reg1, m_reg1, v_reg1,
                                  w_reg2, b_reg2, box_reg);
}

// round 2
// speedup vs baseline: 1.1630x; 1.1630x over previous
#include <cuda_runtime.h>

#define EPSBN 1e-5f
#define HH 300
#define WW 300
#define HW (HH * WW)
#define BB 4
#define HCH 64
#define CBLK 8
#define TX 64
#define TY 16

// Scratch activations (device globals — allocation-guard-safe)
__device__ float g_trunk[(size_t)BB * HCH * HW];
__device__ float g_mid_hm[(size_t)BB * HCH * HW];
__device__ float g_mid_rg[(size_t)BB * HCH * HW];

// ---------------------------------------------------------------------------
// conv3x3 + BN + ReLU. Block: 256 threads, output tile 64x16 pixels x 16 oc
// (oc group selected by blockIdx.z & 3). Each thread: 1x4 pixels x 16 oc.
// ---------------------------------------------------------------------------
template <int CIN>
__global__ __launch_bounds__(256, 2) void conv3x3_kernel(
    const float* __restrict__ in, const float* __restrict__ wgt,
    const float* __restrict__ gg, const float* __restrict__ bbp,
    const float* __restrict__ mm, const float* __restrict__ vv,
    float* __restrict__ out)
{
    __shared__ float s_in[CBLK][18 * 67];   // 18 rows x 66 cols halo, pitch 67
    __shared__ float s_w[CBLK][144];        // [k*16 + oc_local]

    const int tid = threadIdx.x;
    const int tx = tid & 15, ty = tid >> 4;
    const int bx = blockIdx.x * TX, by = blockIdx.y * TY;
    const int b = blockIdx.z >> 2;
    const int oc0 = (blockIdx.z & 3) * 16;

    float acc[64];   // acc[j*4 + px] : oc_local j, pixel px
#pragma unroll
    for (int i = 0; i < 64; i++) acc[i] = 0.f;

    const float* inb = in + (size_t)b * CIN * HW;

    for (int cc = 0; cc < CIN; cc += CBLK) {
        __syncthreads();
        // stage input halo (CBLK channels, 18x66)
        for (int i = tid; i < CBLK * 18 * 66; i += 256) {
            int c = i / 1188, rem = i % 1188;
            int r = rem / 66, col = rem % 66;
            int gy = by - 1 + r, gx = bx - 1 + col;
            float v = 0.f;
            if ((unsigned)gy < HH && (unsigned)gx < WW)
                v = inb[(size_t)(cc + c) * HW + gy * WW + gx];
            s_in[c][r * 67 + col] = v;
        }
        // stage weights for this oc group: s_w[c][k*16 + ocl]
        for (int i = tid; i < CBLK * 144; i += 256) {
            int c = i / 144, j = i % 144;
            int ocl = j / 9, k = j % 9;
            s_w[c][k * 16 + ocl] = wgt[((size_t)(oc0 + ocl) * CIN + cc + c) * 9 + k];
        }
        __syncthreads();

#pragma unroll 1
        for (int c = 0; c < CBLK; c++) {
            float p[18];   // 3 rows x 6 cols
#pragma unroll
            for (int r = 0; r < 3; r++)
#pragma unroll
                for (int q = 0; q < 6; q++)
                    p[r * 6 + q] = s_in[c][(ty + r) * 67 + 4 * tx + q];
            const float4* w4 = (const float4*)s_w[c];
#pragma unroll
            for (int k = 0; k < 9; k++) {
                const int dy = k / 3, dx = k % 3;
#pragma unroll
                for (int g = 0; g < 4; g++) {
                    float4 w = w4[k * 4 + g];
#pragma unroll
                    for (int px = 0; px < 4; px++) {
                        float pv = p[dy * 6 + px + dx];
                        acc[(g * 4 + 0) * 4 + px] += pv * w.x;
                        acc[(g * 4 + 1) * 4 + px] += pv * w.y;
                        acc[(g * 4 + 2) * 4 + px] += pv * w.z;
                        acc[(g * 4 + 3) * 4 + px] += pv * w.w;
                    }
                }
            }
        }
    }

    const int gy = by + ty, gx0 = bx + 4 * tx;
    if (gy < HH && gx0 < WW) {   // gx0 mult of 4, WW mult of 4 -> full float4 in bounds
#pragma unroll
        for (int j = 0; j < 16; j++) {
            int oc = oc0 + j;
            float sc = __ldg(&gg[oc]) * rsqrtf(__ldg(&vv[oc]) + EPSBN);
            float sh = __ldg(&bbp[oc]) - __ldg(&mm[oc]) * sc;
            float4 o;
            o.x = fmaxf(acc[j * 4 + 0] * sc + sh, 0.f);
            o.y = fmaxf(acc[j * 4 + 1] * sc + sh, 0.f);
            o.z = fmaxf(acc[j * 4 + 2] * sc + sh, 0.f);
            o.w = fmaxf(acc[j * 4 + 3] * sc + sh, 0.f);
            *(float4*)&out[(size_t)(b * HCH + oc) * HW + gy * WW + gx0] = o;
        }
    }
}

// ---------------------------------------------------------------------------
// Fused 1x1 convs for both heads: reads both mid activations, writes d_out.
// ---------------------------------------------------------------------------
__global__ __launch_bounds__(256) void head1x1_kernel(
    const float* __restrict__ w_hm2, const float* __restrict__ b_hm2,
    const float* __restrict__ w_rg2, const float* __restrict__ b_rg2,
    float* __restrict__ out)
{
    __shared__ float s_wh[3 * 64];
    __shared__ float s_wr[8 * 64];
    const int tid = threadIdx.x;
    for (int i = tid; i < 192; i += 256) s_wh[i] = w_hm2[i];
    for (int i = tid; i < 512; i += 256) s_wr[i] = w_rg2[i];
    __syncthreads();

    size_t idx = (size_t)blockIdx.x * 256 + tid;
    if (idx >= (size_t)BB * HW) return;
    int b = (int)(idx / HW);
    int p = (int)(idx % HW);

    const float* mh = g_mid_hm + (size_t)b * HCH * HW + p;
    const float* mr = g_mid_rg + (size_t)b * HCH * HW + p;

    float sh0 = b_hm2[0], sh1 = b_hm2[1], sh2 = b_hm2[2];
    float sr[8];
#pragma unroll
    for (int j = 0; j < 8; j++) sr[j] = b_rg2[j];

#pragma unroll 4
    for (int c = 0; c < 64; c++) {
        float a = mh[(size_t)c * HW];
        sh0 += a * s_wh[0 * 64 + c];
        sh1 += a * s_wh[1 * 64 + c];
        sh2 += a * s_wh[2 * 64 + c];
        float r = mr[(size_t)c * HW];
#pragma unroll
        for (int j = 0; j < 8; j++) sr[j] += r * s_wr[j * 64 + c];
    }

    float* hm = out;
    float* rg = out + (size_t)BB * 3 * HW;
    hm[((size_t)b * 3 + 0) * HW + p] = sh0;
    hm[((size_t)b * 3 + 1) * HW + p] = sh1;
    hm[((size_t)b * 3 + 2) * HW + p] = sh2;
#pragma unroll
    for (int j = 0; j < 8; j++)
        rg[((size_t)b * 8 + j) * HW + p] = sr[j];
}

// ---------------------------------------------------------------------------
extern "C" void kernel_launch(void* const* d_in, const int* in_sizes, int n_in,
                              void* d_out, int out_size)
{
    const float* bev    = (const float*)d_in[0];
    const float* w_sh   = (const float*)d_in[1];
    const float* g_sh   = (const float*)d_in[2];
    const float* b_sh   = (const float*)d_in[3];
    const float* m_sh   = (const float*)d_in[4];
    const float* v_sh   = (const float*)d_in[5];
    const float* w_hm1  = (const float*)d_in[6];
    const float* g_hm1  = (const float*)d_in[7];
    const float* b_hm1  = (const float*)d_in[8];
    const float* m_hm1  = (const float*)d_in[9];
    const float* v_hm1  = (const float*)d_in[10];
    const float* w_hm2  = (const float*)d_in[11];
    const float* b_hm2  = (const float*)d_in[12];
    const float* w_rg1  = (const float*)d_in[13];
    const float* g_rg1  = (const float*)d_in[14];
    const float* b_rg1  = (const float*)d_in[15];
    const float* m_rg1  = (const float*)d_in[16];
    const float* v_rg1  = (const float*)d_in[17];
    const float* w_rg2  = (const float*)d_in[18];
    const float* b_rg2  = (const float*)d_in[19];

    float *trunk, *midh, *midr;
    cudaGetSymbolAddress((void**)&trunk, g_trunk);
    cudaGetSymbolAddress((void**)&midh, g_mid_hm);
    cudaGetSymbolAddress((void**)&midr, g_mid_rg);

    dim3 grid((WW + TX - 1) / TX, (HH + TY - 1) / TY, BB * 4);   // 5 x 19 x 16

    conv3x3_kernel<256><<<grid, 256>>>(bev, w_sh, g_sh, b_sh, m_sh, v_sh, trunk);
    conv3x3_kernel<64><<<grid, 256>>>(trunk, w_hm1, g_hm1, b_hm1, m_hm1, v_hm1, midh);
    conv3x3_kernel<64><<<grid, 256>>>(trunk, w_rg1, g_rg1, b_rg1, m_rg1, v_rg1, midr);

    int npix = BB * HW;
    head1x1_kernel<<<(npix + 255) / 256, 256>>>(w_hm2, b_hm2, w_rg2, b_rg2, (float*)d_out);
}